// round 13
// baseline (speedup 1.0000x reference)
#include <cuda_runtime.h>

// BidirectionalLSTMComplex: S=1024, B=2048, H=32, IN=1, OUT=1
// Round 13: R10 arithmetic, ANTI-PHASE halves. Each iteration:
//   Region 1: F computes gates(t)     | B finalizes gates(t-1)
//   Region 2: F finalizes gates(t)+out| B computes gates(t)
// Every region mixes FMA-dense and MUFU warps on each SMSP.
// hf1: depth-4 ring. hb1: parity pair. c-states stay in smem (R12 lesson).

#define S_LEN 1024
#define B_TOT 2048
#define HID   32
#define GATES 128
#define NB    7
#define NCTA  296
#define HP    36

typedef unsigned long long u64;

__device__ __forceinline__ void fma2(u64 &acc, u64 a, u64 b) {
    asm("fma.rn.f32x2 %0, %1, %2, %3;" : "=l"(acc) : "l"(a), "l"(b), "l"(acc));
}
__device__ __forceinline__ void add2(u64 &a, u64 b) {
    asm("add.rn.f32x2 %0, %1, %2;" : "=l"(a) : "l"(a), "l"(b));
}
__device__ __forceinline__ float hsum2(u64 v) {
    float lo, hi;
    asm("mov.b64 {%0,%1}, %2;" : "=f"(lo), "=f"(hi) : "l"(v));
    return lo + hi;
}
__device__ __forceinline__ float tanh_fast(float x) {
    float y;
    asm("tanh.approx.f32 %0, %1;" : "=f"(y) : "f"(x));
    return y;
}
__device__ __forceinline__ float sigm(float x) {
    return fmaf(tanh_fast(x * 0.5f), 0.5f, 0.5f);
}

__device__ __forceinline__ void load_row(u64 *w, const float *base) {
    const ulonglong2 *p = (const ulonglong2 *)base;
#pragma unroll
    for (int i = 0; i < 8; i++) {
        ulonglong2 q = p[i];
        w[2 * i]     = q.x;
        w[2 * i + 1] = q.y;
    }
}

__device__ __forceinline__ void cell1(const float *g, float *c, float *h, int m) {
    float gi = g[m], gf = g[m + 32], gg = g[m + 64], go = g[m + 96];
    float c2 = sigm(gf) * c[m] + sigm(gi) * tanh_fast(gg);
    c[m] = c2;
    h[m] = sigm(go) * tanh_fast(c2);
}

__device__ __forceinline__ void cell2(const float *g0, float *c0, float *h0,
                                      const float *g1, float *c1, float *h1, int m) {
    float ai = g0[m], af = g0[m + 32], ag = g0[m + 64], ao = g0[m + 96];
    float bi = g1[m], bf = g1[m + 32], bg = g1[m + 64], bo = g1[m + 96];
    float sfa = sigm(af), sfb = sigm(bf);
    float sia = sigm(ai), sib = sigm(bi);
    float tga = tanh_fast(ag), tgb = tanh_fast(bg);
    float soa = sigm(ao), sob = sigm(bo);
    float c2a = sfa * c0[m] + sia * tga;
    float c2b = sfb * c1[m] + sib * tgb;
    c0[m] = c2a; c1[m] = c2b;
    h0[m] = soa * tanh_fast(c2a);
    h1[m] = sob * tanh_fast(c2b);
}

__global__ void __launch_bounds__(256, 2)
lstm_kernel(const float *__restrict__ x,
            const float *__restrict__ Wih_f0, const float *__restrict__ Whh_f0, const float *__restrict__ b_f0,
            const float *__restrict__ Wih_f1, const float *__restrict__ Whh_f1, const float *__restrict__ b_f1,
            const float *__restrict__ Wih_b0, const float *__restrict__ Whh_b0, const float *__restrict__ b_b0,
            const float *__restrict__ Wih_b1, const float *__restrict__ Whh_b1, const float *__restrict__ b_b1,
            const float *__restrict__ Wlin,   const float *__restrict__ blin,
            const int *__restrict__ future_p,
            float *__restrict__ out)
{
    const int tid  = threadIdx.x;
    const int j    = tid & 127;
    const bool isF = tid < 128;
    const int nb0  = blockIdx.x * NB;

    __shared__ __align__(16) float hf0s[NB][HP];
    __shared__ __align__(16) float hf1s[4][NB][HP];   // depth-4 ring
    __shared__ __align__(16) float hb0s[NB][HP];
    __shared__ __align__(16) float hb1s[2][NB][HP];   // parity pair
    __shared__ float cf0s[NB][HID], cf1s[NB][HID], cb0s[NB][HID], cb1s[NB][HID];
    __shared__ float gF0[NB][GATES], gF1[NB][GATES];
    __shared__ float gB0[NB][GATES], gB1[NB][GATES];
    __shared__ float xs[NB], xbs[NB];
    __shared__ __align__(16) float wls[2 * HID];
    __shared__ float blin_s;

    u64 w0[16], w1[16], w2[16];
    float bias0, bias1, wx;
    if (isF) {
        load_row(w0, Whh_f0 + j * HID);
        load_row(w1, Wih_f1 + j * HID);
        load_row(w2, Whh_f1 + j * HID);
        bias0 = b_f0[j]; bias1 = b_f1[j]; wx = Wih_f0[j];
    } else {
        load_row(w0, Whh_b0 + j * HID);
        load_row(w1, Wih_b1 + j * HID);
        load_row(w2, Whh_b1 + j * HID);   // on hf1 (replicated bug)
        bias0 = b_b0[j]; bias1 = b_b1[j]; wx = Wih_b0[j];
    }
    const int fut = future_p[0];
    const float *xbase = x + nb0;
    const bool jval = (j < NB) && (nb0 + j < B_TOT);

    for (int i = tid; i < NB * HP; i += 256) {
        ((float *)hf0s)[i] = 0.f; ((float *)hb0s)[i] = 0.f;
    }
    for (int i = tid; i < 4 * NB * HP; i += 256) ((float *)hf1s)[i] = 0.f;
    for (int i = tid; i < 2 * NB * HP; i += 256) ((float *)hb1s)[i] = 0.f;
    for (int i = tid; i < NB * HID; i += 256) {
        ((float *)cf0s)[i] = 0.f; ((float *)cf1s)[i] = 0.f;
        ((float *)cb0s)[i] = 0.f; ((float *)cb1s)[i] = 0.f;
    }
    if (tid < 2 * HID) wls[tid] = Wlin[tid];
    if (tid == 0) blin_s = blin[0];

    int rb = fut % S_LEN; if (rb < 0) rb += S_LEN;     // backward index for t=0

    if (tid < NB) {
        xs[tid] = jval ? xbase[tid] : 0.f;
    } else if (tid >= 128 && tid < 128 + NB) {
        xbs[tid - 128] = jval ? xbase[rb * B_TOT + (tid - 128)] : 0.f;
    }
    rb--; if (rb < 0) rb += S_LEN;                     // index for t=1

    __syncthreads();

    const int m  = j & 31;
    const int ng = j >> 5;

    // prologue: f0_0 from zero state
    if (isF) {
#pragma unroll
        for (int n = 0; n < NB; n++) gF0[n][j] = bias0 + wx * xs[n];
    }
    __syncthreads();
    if (isF) {
        if (ng < 3) cell2(gF0[ng], cf0s[ng], hf0s[ng],
                          gF0[ng + 4], cf0s[ng + 4], hf0s[ng + 4], m);
        else        cell1(gF0[3], cf0s[3], hf0s[3], m);
    }
    if (tid < NB) xs[tid] = jval ? xbase[B_TOT + tid] : 0.f;   // x_1
    __syncthreads();

    float xreg = 0.f, xbreg = 0.f;   // persist across regions

    // Iter t:  R1: F-comp(t) | B-fin(gates t-1)   R2: F-fin(t)+out_{t-2} | B-comp(t)
    for (int t = 0; t < S_LEN + 2; t++) {
        // ================= Region 1 =================
        if (isF) {
            if (t < S_LEN) {
                xreg = (jval && t + 2 < S_LEN) ? xbase[(t + 2) * B_TOT + j] : 0.f;
                const float *hvb = hf1s[(t + 3) & 3][0];   // hf1_{t-1}
#pragma unroll
                for (int n = 0; n < NB; n++) {
                    u64 a0 = 0, a1 = 0, a2 = 0, a3 = 0, a4 = 0, a5 = 0;
                    const ulonglong2 *hu = (const ulonglong2 *)hf0s[n];
                    const ulonglong2 *hv = (const ulonglong2 *)(hvb + n * HP);
#pragma unroll
                    for (int c = 0; c < 8; c++) {
                        ulonglong2 u = hu[c];
                        fma2(a0, w0[2 * c],     u.x);
                        fma2(a1, w0[2 * c + 1], u.y);
                        fma2(a2, w1[2 * c],     u.x);
                        fma2(a3, w1[2 * c + 1], u.y);
                        ulonglong2 v = hv[c];
                        fma2(a4, w2[2 * c],     v.x);
                        fma2(a5, w2[2 * c + 1], v.y);
                    }
                    add2(a0, a1);
                    gF0[n][j] = hsum2(a0) + bias0 + wx * xs[n];     // f0_{t+1}
                    add2(a2, a3); add2(a4, a5); add2(a2, a4);
                    gF1[n][j] = hsum2(a2) + bias1;                  // f1_t
                }
            }
        } else {
            const int p = t - 1;   // finalize gates computed at iter p
            if (p >= 0) {
                if (p < S_LEN) {
                    if (ng < 3) cell2(gB0[ng], cb0s[ng], hb0s[ng],
                                      gB0[ng + 4], cb0s[ng + 4], hb0s[ng + 4], m);  // b0_p
                    else        cell1(gB0[3], cb0s[3], hb0s[3], m);
                    if (j < NB) xbs[j] = xbreg;                                     // xb_{p+1}
                }
                if (p >= 1 && p <= S_LEN) {
                    // b1_{p-1} -> slot (p-1)&1
                    const int sb = (p + 1) & 1;
                    if (ng < 3) cell2(gB1[ng], cb1s[ng], hb1s[sb][ng],
                                      gB1[ng + 4], cb1s[ng + 4], hb1s[sb][ng + 4], m);
                    else        cell1(gB1[3], cb1s[3], hb1s[sb][3], m);
                }
            }
        }
        __syncthreads();

        // ================= Region 2 =================
        if (isF) {
            if (t < S_LEN) {
                if (ng < 3) {
                    cell2(gF0[ng], cf0s[ng], hf0s[ng],
                          gF0[ng + 4], cf0s[ng + 4], hf0s[ng + 4], m);            // f0_{t+1}
                    cell2(gF1[ng], cf1s[ng], hf1s[t & 3][ng],
                          gF1[ng + 4], cf1s[ng + 4], hf1s[t & 3][ng + 4], m);     // f1_t
                } else {
                    cell2(gF0[3], cf0s[3], hf0s[3],
                          gF1[3], cf1s[3], hf1s[t & 3][3], m);
                }
                if (j < NB) xs[j] = xreg;                                          // x_{t+2}
            }
            // out_{t-2}: hf1_{t-2} = slot (t-2)&3, hb1_{t-2} = slot t&1 (fin'd R1)
            if (t >= 2 && j >= 120) {
                int n = j - 120;
                if (n < NB && nb0 + n < B_TOT) {
                    const ulonglong2 *pf = (const ulonglong2 *)hf1s[(t + 2) & 3][n];
                    const ulonglong2 *pk = (const ulonglong2 *)hb1s[t & 1][n];
                    const ulonglong2 *wf = (const ulonglong2 *)wls;
                    u64 acc = 0, acc2 = 0;
#pragma unroll
                    for (int c = 0; c < 8; c++) {
                        ulonglong2 u = pf[c], wu = wf[c];
                        fma2(acc,  wu.x, u.x);
                        fma2(acc2, wu.y, u.y);
                        ulonglong2 v = pk[c], wv = wf[c + 8];
                        fma2(acc,  wv.x, v.x);
                        fma2(acc2, wv.y, v.y);
                    }
                    add2(acc, acc2);
                    out[(nb0 + n) * S_LEN + (t - 2)] = hsum2(acc) + blin_s;
                }
            }
        } else {
            if (t <= S_LEN) {
                xbreg = (jval && t + 1 < S_LEN) ? xbase[rb * B_TOT + j] : 0.f;
                const float *hvb = hf1s[(t + 3) & 3][0];   // hf1_{t-1} (F writes t&3 concurrently)
#pragma unroll
                for (int n = 0; n < NB; n++) {
                    u64 a0 = 0, a1 = 0, a2 = 0, a3 = 0, a4 = 0, a5 = 0;
                    const ulonglong2 *hu = (const ulonglong2 *)hb0s[n];
                    const ulonglong2 *hv = (const ulonglong2 *)(hvb + n * HP);
#pragma unroll
                    for (int c = 0; c < 8; c++) {
                        ulonglong2 u = hu[c];
                        fma2(a0, w0[2 * c],     u.x);
                        fma2(a1, w0[2 * c + 1], u.y);
                        fma2(a2, w1[2 * c],     u.x);
                        fma2(a3, w1[2 * c + 1], u.y);
                        ulonglong2 v = hv[c];
                        fma2(a4, w2[2 * c],     v.x);
                        fma2(a5, w2[2 * c + 1], v.y);
                    }
                    add2(a0, a1);
                    gB0[n][j] = hsum2(a0) + bias0 + wx * xbs[n];    // b0_t
                    add2(a2, a3); add2(a4, a5); add2(a2, a4);
                    gB1[n][j] = hsum2(a2) + bias1;                  // b1_{t-1}
                }
            }
            rb--; if (rb < 0) rb += S_LEN;
        }
        __syncthreads();
    }
}

extern "C" void kernel_launch(void *const *d_in, const int *in_sizes, int n_in,
                              void *d_out, int out_size)
{
    const float *x      = (const float *)d_in[0];
    const float *Wih_f0 = (const float *)d_in[1];
    const float *Whh_f0 = (const float *)d_in[2];
    const float *b_f0   = (const float *)d_in[3];
    const float *Wih_f1 = (const float *)d_in[4];
    const float *Whh_f1 = (const float *)d_in[5];
    const float *b_f1   = (const float *)d_in[6];
    const float *Wih_b0 = (const float *)d_in[7];
    const float *Whh_b0 = (const float *)d_in[8];
    const float *b_b0   = (const float *)d_in[9];
    const float *Wih_b1 = (const float *)d_in[10];
    const float *Whh_b1 = (const float *)d_in[11];
    const float *b_b1   = (const float *)d_in[12];
    const float *Wlin   = (const float *)d_in[13];
    const float *blin   = (const float *)d_in[14];
    const int   *future = (const int *)d_in[15];
    float *out = (float *)d_out;

    lstm_kernel<<<NCTA, 256>>>(x,
                               Wih_f0, Whh_f0, b_f0,
                               Wih_f1, Whh_f1, b_f1,
                               Wih_b0, Whh_b0, b_b0,
                               Wih_b1, Whh_b1, b_b1,
                               Wlin, blin, future, out);
}

// round 15
// speedup vs baseline: 1.1001x; 1.1001x over previous
#include <cuda_runtime.h>

// BidirectionalLSTMComplex: S=1024, B=2048, H=32, IN=1, OUT=1
// Round 14: batch-subset interleave. G0={0..3}, G1={4..6} run half a step
// out of phase. Each phase mixes compute(FMA) + finalize(MUFU) per thread:
//   Phase E(t): compute G0(t) + finalize G1(t-1)   [both halves]
//   Phase O(t): finalize G0(t) + compute G1(t)     [both halves]
// hf1 parity pair; hb1/gates single-buffered (disjoint-n discipline).

#define S_LEN 1024
#define B_TOT 2048
#define HID   32
#define GATES 128
#define NB    7
#define NCTA  296
#define HP    36

typedef unsigned long long u64;

__device__ __forceinline__ void fma2(u64 &acc, u64 a, u64 b) {
    asm("fma.rn.f32x2 %0, %1, %2, %3;" : "=l"(acc) : "l"(a), "l"(b), "l"(acc));
}
__device__ __forceinline__ void add2(u64 &a, u64 b) {
    asm("add.rn.f32x2 %0, %1, %2;" : "=l"(a) : "l"(a), "l"(b));
}
__device__ __forceinline__ float hsum2(u64 v) {
    float lo, hi;
    asm("mov.b64 {%0,%1}, %2;" : "=f"(lo), "=f"(hi) : "l"(v));
    return lo + hi;
}
__device__ __forceinline__ float tanh_fast(float x) {
    float y;
    asm("tanh.approx.f32 %0, %1;" : "=f"(y) : "f"(x));
    return y;
}
__device__ __forceinline__ float sigm(float x) {
    return fmaf(tanh_fast(x * 0.5f), 0.5f, 0.5f);
}

__device__ __forceinline__ void load_row(u64 *w, const float *base) {
    const ulonglong2 *p = (const ulonglong2 *)base;
#pragma unroll
    for (int i = 0; i < 8; i++) {
        ulonglong2 q = p[i];
        w[2 * i]     = q.x;
        w[2 * i + 1] = q.y;
    }
}

__device__ __forceinline__ void cell1(const float *g, float *c, float *h, int m) {
    float gi = g[m], gf = g[m + 32], gg = g[m + 64], go = g[m + 96];
    float c2 = sigm(gf) * c[m] + sigm(gi) * tanh_fast(gg);
    c[m] = c2;
    h[m] = sigm(go) * tanh_fast(c2);
}

__device__ __forceinline__ void cell2(const float *g0, float *c0, float *h0,
                                      const float *g1, float *c1, float *h1, int m) {
    float ai = g0[m], af = g0[m + 32], ag = g0[m + 64], ao = g0[m + 96];
    float bi = g1[m], bf = g1[m + 32], bg = g1[m + 64], bo = g1[m + 96];
    float sfa = sigm(af), sfb = sigm(bf);
    float sia = sigm(ai), sib = sigm(bi);
    float tga = tanh_fast(ag), tgb = tanh_fast(bg);
    float soa = sigm(ao), sob = sigm(bo);
    float c2a = sfa * c0[m] + sia * tga;
    float c2b = sfb * c1[m] + sib * tgb;
    c0[m] = c2a; c1[m] = c2b;
    h0[m] = soa * tanh_fast(c2a);
    h1[m] = sob * tanh_fast(c2b);
}

// compute gates for batches [N0,N1): g0 = layer0 gate (+wx*x), g1 = layer1 gate
template <int N0, int N1>
__device__ __forceinline__ void compute_gates(
    const u64 *w0, const u64 *w1, const u64 *w2,
    const float *h_u, const float *h_v,
    float (*g0)[GATES], float (*g1)[GATES],
    const float *xarr, float bias0, float bias1, float wx, int j)
{
#pragma unroll
    for (int n = N0; n < N1; n++) {
        u64 a0 = 0, a1 = 0, a2 = 0, a3 = 0, a4 = 0, a5 = 0;
        const ulonglong2 *hu = (const ulonglong2 *)(h_u + n * HP);
        const ulonglong2 *hv = (const ulonglong2 *)(h_v + n * HP);
#pragma unroll
        for (int c = 0; c < 8; c++) {
            ulonglong2 u = hu[c];
            fma2(a0, w0[2 * c],     u.x);
            fma2(a1, w0[2 * c + 1], u.y);
            fma2(a2, w1[2 * c],     u.x);
            fma2(a3, w1[2 * c + 1], u.y);
            ulonglong2 v = hv[c];
            fma2(a4, w2[2 * c],     v.x);
            fma2(a5, w2[2 * c + 1], v.y);
        }
        add2(a0, a1);
        g0[n][j] = hsum2(a0) + bias0 + wx * xarr[n];
        add2(a2, a3); add2(a4, a5); add2(a2, a4);
        g1[n][j] = hsum2(a2) + bias1;
    }
}

__device__ __forceinline__ void out_dot(float *outp, const float *hf, const float *hb,
                                        const float *wls, float blin_s)
{
    const ulonglong2 *pf = (const ulonglong2 *)hf;
    const ulonglong2 *pk = (const ulonglong2 *)hb;
    const ulonglong2 *wf = (const ulonglong2 *)wls;
    u64 acc = 0, acc2 = 0;
#pragma unroll
    for (int c = 0; c < 8; c++) {
        ulonglong2 u = pf[c], wu = wf[c];
        fma2(acc,  wu.x, u.x);
        fma2(acc2, wu.y, u.y);
        ulonglong2 v = pk[c], wv = wf[c + 8];
        fma2(acc,  wv.x, v.x);
        fma2(acc2, wv.y, v.y);
    }
    add2(acc, acc2);
    *outp = hsum2(acc) + blin_s;
}

__global__ void __launch_bounds__(256, 2)
lstm_kernel(const float *__restrict__ x,
            const float *__restrict__ Wih_f0, const float *__restrict__ Whh_f0, const float *__restrict__ b_f0,
            const float *__restrict__ Wih_f1, const float *__restrict__ Whh_f1, const float *__restrict__ b_f1,
            const float *__restrict__ Wih_b0, const float *__restrict__ Whh_b0, const float *__restrict__ b_b0,
            const float *__restrict__ Wih_b1, const float *__restrict__ Whh_b1, const float *__restrict__ b_b1,
            const float *__restrict__ Wlin,   const float *__restrict__ blin,
            const int *__restrict__ future_p,
            float *__restrict__ out)
{
    const int tid  = threadIdx.x;
    const int j    = tid & 127;
    const bool isF = tid < 128;
    const int nb0  = blockIdx.x * NB;

    __shared__ __align__(16) float hf0s[NB][HP];
    __shared__ __align__(16) float hf1s[2][NB][HP];   // parity pair
    __shared__ __align__(16) float hb0s[NB][HP];
    __shared__ __align__(16) float hb1s[NB][HP];      // single buffer
    __shared__ float cf0s[NB][HID], cf1s[NB][HID], cb0s[NB][HID], cb1s[NB][HID];
    __shared__ float gF0[NB][GATES], gF1[NB][GATES];
    __shared__ float gB0[NB][GATES], gB1[NB][GATES];
    __shared__ float xs[NB], xbs[NB];
    __shared__ __align__(16) float wls[2 * HID];
    __shared__ float blin_s;

    u64 w0[16], w1[16], w2[16];
    float bias0, bias1, wx;
    if (isF) {
        load_row(w0, Whh_f0 + j * HID);
        load_row(w1, Wih_f1 + j * HID);
        load_row(w2, Whh_f1 + j * HID);
        bias0 = b_f0[j]; bias1 = b_f1[j]; wx = Wih_f0[j];
    } else {
        load_row(w0, Whh_b0 + j * HID);
        load_row(w1, Wih_b1 + j * HID);
        load_row(w2, Whh_b1 + j * HID);   // on hf1 (replicated bug)
        bias0 = b_b0[j]; bias1 = b_b1[j]; wx = Wih_b0[j];
    }
    const int fut = future_p[0];
    const float *xbase = x + nb0;
    const bool jval = (j < NB) && (nb0 + j < B_TOT);

    for (int i = tid; i < NB * HP; i += 256) {
        ((float *)hf0s)[i] = 0.f; ((float *)hb0s)[i] = 0.f; ((float *)hb1s)[i] = 0.f;
    }
    for (int i = tid; i < 2 * NB * HP; i += 256) ((float *)hf1s)[i] = 0.f;
    for (int i = tid; i < NB * HID; i += 256) {
        ((float *)cf0s)[i] = 0.f; ((float *)cf1s)[i] = 0.f;
        ((float *)cb0s)[i] = 0.f; ((float *)cb1s)[i] = 0.f;
    }
    if (tid < 2 * HID) wls[tid] = Wlin[tid];
    if (tid == 0) blin_s = blin[0];

    int rbE = fut % S_LEN; if (rbE < 0) rbE += S_LEN;          // idx(t) at iter t
    int rbO = rbE - 1;     if (rbO < 0) rbO += S_LEN;          // idx(t+1) at iter t

    if (tid < NB) {
        xs[tid] = jval ? xbase[tid] : 0.f;                      // x_0
    } else if (tid >= 128 && tid < 128 + NB) {
        xbs[tid - 128] = jval ? xbase[rbE * B_TOT + (tid - 128)] : 0.f;   // xb_0
    }
    __syncthreads();

    const int m  = j & 31;
    const int ng = j >> 5;

    // prologue: f0_0 from zero state (all n)
    if (isF) {
#pragma unroll
        for (int n = 0; n < NB; n++) gF0[n][j] = bias0 + wx * xs[n];
    }
    __syncthreads();
    if (isF) {
        if (ng < 3) {
            cell1(gF0[ng],     cf0s[ng],     hf0s[ng],     m);
            cell1(gF0[ng + 4], cf0s[ng + 4], hf0s[ng + 4], m);
        } else {
            cell1(gF0[3], cf0s[3], hf0s[3], m);
        }
    }
    if (tid < NB) xs[tid] = jval ? xbase[B_TOT + tid] : 0.f;    // x_1 (all n)
    __syncthreads();

    for (int t = 0; t < S_LEN + 2; t++) {
        const int sl_prev = (t + 1) & 1;   // (t-1)&1
        const int sl_cur  = t & 1;

        // ================= Phase E: compute G0(t) + finalize G1(t-1) =================
        if (isF) {
            if (t < S_LEN) {
                compute_gates<0, 4>(w0, w1, w2, hf0s[0], hf1s[sl_prev][0],
                                    gF0, gF1, xs, bias0, bias1, wx, j);
                if (j >= 4 && j < NB)
                    xs[j] = (jval && t + 1 < S_LEN) ? xbase[(t + 1) * B_TOT + j] : 0.f;
            }
            if (t >= 1 && t <= S_LEN && ng < 3) {      // fin G1, s = t-1 < S
                int n = 4 + ng;
                cell2(gF0[n], cf0s[n], hf0s[n],
                      gF1[n], cf1s[n], hf1s[sl_prev][n], m);
            }
        } else {
            if (t <= S_LEN) {
                compute_gates<0, 4>(w0, w1, w2, hb0s[0], hf1s[sl_prev][0],
                                    gB0, gB1, xbs, bias0, bias1, wx, j);
                if (j >= 4 && j < NB)
                    xbs[j] = (jval && t < S_LEN) ? xbase[rbE * B_TOT + j] : 0.f;
            }
            if (t >= 1 && ng < 3) {                    // fin G1, s = t-1 in [0, S]
                int n = 4 + ng;
                const int s = t - 1;
                if (s >= 1 && s < S_LEN)
                    cell2(gB0[n], cb0s[n], hb0s[n],
                          gB1[n], cb1s[n], hb1s[n], m);
                else if (s == 0)
                    cell1(gB0[n], cb0s[n], hb0s[n], m);
                else                                   // s == S_LEN
                    cell1(gB1[n], cb1s[n], hb1s[n], m);
            }
            if (t >= 2 && j >= 96 && j < 100) {        // out_{t-2}[G0]
                int n = j - 96;
                if (nb0 + n < B_TOT)
                    out_dot(&out[(nb0 + n) * S_LEN + (t - 2)],
                            hf1s[sl_cur][n], hb1s[n], wls, blin_s);
            }
        }
        __syncthreads();

        // ================= Phase O: finalize G0(t) + compute G1(t) =================
        if (isF) {
            if (t < S_LEN) {
                compute_gates<4, NB>(w0, w1, w2, hf0s[0], hf1s[sl_prev][0],
                                     gF0, gF1, xs, bias0, bias1, wx, j);
                if (j < 4)
                    xs[j] = (jval && t + 2 < S_LEN) ? xbase[(t + 2) * B_TOT + j] : 0.f;
                int n = ng;                            // fin G0(t)
                cell2(gF0[n], cf0s[n], hf0s[n],
                      gF1[n], cf1s[n], hf1s[sl_cur][n], m);
            }
        } else {
            if (t <= S_LEN) {
                compute_gates<4, NB>(w0, w1, w2, hb0s[0], hf1s[sl_prev][0],
                                     gB0, gB1, xbs, bias0, bias1, wx, j);
                if (j < 4)
                    xbs[j] = (jval && t + 1 < S_LEN) ? xbase[rbO * B_TOT + j] : 0.f;
                int n = ng;                            // fin G0, s = t in [0, S]
                const int s = t;
                if (s >= 1 && s < S_LEN)
                    cell2(gB0[n], cb0s[n], hb0s[n],
                          gB1[n], cb1s[n], hb1s[n], m);
                else if (s == 0)
                    cell1(gB0[n], cb0s[n], hb0s[n], m);
                else                                   // s == S_LEN
                    cell1(gB1[n], cb1s[n], hb1s[n], m);
            }
            if (t >= 2 && j >= 100 && j < 96 + NB) {   // out_{t-2}[G1]
                int n = j - 96;
                if (nb0 + n < B_TOT)
                    out_dot(&out[(nb0 + n) * S_LEN + (t - 2)],
                            hf1s[sl_cur][n], hb1s[n], wls, blin_s);
            }
            rbE--; if (rbE < 0) rbE += S_LEN;
            rbO--; if (rbO < 0) rbO += S_LEN;
        }
        __syncthreads();
    }
}

extern "C" void kernel_launch(void *const *d_in, const int *in_sizes, int n_in,
                              void *d_out, int out_size)
{
    const float *x      = (const float *)d_in[0];
    const float *Wih_f0 = (const float *)d_in[1];
    const float *Whh_f0 = (const float *)d_in[2];
    const float *b_f0   = (const float *)d_in[3];
    const float *Wih_f1 = (const float *)d_in[4];
    const float *Whh_f1 = (const float *)d_in[5];
    const float *b_f1   = (const float *)d_in[6];
    const float *Wih_b0 = (const float *)d_in[7];
    const float *Whh_b0 = (const float *)d_in[8];
    const float *b_b0   = (const float *)d_in[9];
    const float *Wih_b1 = (const float *)d_in[10];
    const float *Whh_b1 = (const float *)d_in[11];
    const float *b_b1   = (const float *)d_in[12];
    const float *Wlin   = (const float *)d_in[13];
    const float *blin   = (const float *)d_in[14];
    const int   *future = (const int *)d_in[15];
    float *out = (float *)d_out;

    lstm_kernel<<<NCTA, 256>>>(x,
                               Wih_f0, Whh_f0, b_f0,
                               Wih_f1, Whh_f1, b_f1,
                               Wih_b0, Whh_b0, b_b0,
                               Wih_b1, Whh_b1, b_b1,
                               Wlin, blin, future, out);
}

// round 16
// speedup vs baseline: 1.2843x; 1.1674x over previous
#include <cuda_runtime.h>

// BidirectionalLSTMComplex: S=1024, B=2048, H=32, IN=1, OUT=1
// Round 16: R10 verbatim EXCEPT b1 finalize deferred into B's next compute
// region (MUFU moved from MUFU-bound finalize into fma-bound compute).
// gB1 parity pair; hf1 depth-4 ring; out-dot at lag 3.

#define S_LEN 1024
#define B_TOT 2048
#define HID   32
#define GATES 128
#define NB    7
#define NCTA  296
#define HP    36

typedef unsigned long long u64;

__device__ __forceinline__ void fma2(u64 &acc, u64 a, u64 b) {
    asm("fma.rn.f32x2 %0, %1, %2, %3;" : "=l"(acc) : "l"(a), "l"(b), "l"(acc));
}
__device__ __forceinline__ void add2(u64 &a, u64 b) {
    asm("add.rn.f32x2 %0, %1, %2;" : "=l"(a) : "l"(a), "l"(b));
}
__device__ __forceinline__ float hsum2(u64 v) {
    float lo, hi;
    asm("mov.b64 {%0,%1}, %2;" : "=f"(lo), "=f"(hi) : "l"(v));
    return lo + hi;
}
__device__ __forceinline__ float tanh_fast(float x) {
    float y;
    asm("tanh.approx.f32 %0, %1;" : "=f"(y) : "f"(x));
    return y;
}
__device__ __forceinline__ float sigm(float x) {
    return fmaf(tanh_fast(x * 0.5f), 0.5f, 0.5f);
}

__device__ __forceinline__ void load_row(u64 *w, const float *base) {
    const ulonglong2 *p = (const ulonglong2 *)base;
#pragma unroll
    for (int i = 0; i < 8; i++) {
        ulonglong2 q = p[i];
        w[2 * i]     = q.x;
        w[2 * i + 1] = q.y;
    }
}

__device__ __forceinline__ void cell1(const float *g, float *c, float *h, int m) {
    float gi = g[m], gf = g[m + 32], gg = g[m + 64], go = g[m + 96];
    float c2 = sigm(gf) * c[m] + sigm(gi) * tanh_fast(gg);
    c[m] = c2;
    h[m] = sigm(go) * tanh_fast(c2);
}

__device__ __forceinline__ void cell2(const float *g0, float *c0, float *h0,
                                      const float *g1, float *c1, float *h1, int m) {
    float ai = g0[m], af = g0[m + 32], ag = g0[m + 64], ao = g0[m + 96];
    float bi = g1[m], bf = g1[m + 32], bg = g1[m + 64], bo = g1[m + 96];
    float sfa = sigm(af), sfb = sigm(bf);
    float sia = sigm(ai), sib = sigm(bi);
    float tga = tanh_fast(ag), tgb = tanh_fast(bg);
    float soa = sigm(ao), sob = sigm(bo);
    float c2a = sfa * c0[m] + sia * tga;
    float c2b = sfb * c1[m] + sib * tgb;
    c0[m] = c2a; c1[m] = c2b;
    h0[m] = soa * tanh_fast(c2a);
    h1[m] = sob * tanh_fast(c2b);
}

__global__ void __launch_bounds__(256, 2)
lstm_kernel(const float *__restrict__ x,
            const float *__restrict__ Wih_f0, const float *__restrict__ Whh_f0, const float *__restrict__ b_f0,
            const float *__restrict__ Wih_f1, const float *__restrict__ Whh_f1, const float *__restrict__ b_f1,
            const float *__restrict__ Wih_b0, const float *__restrict__ Whh_b0, const float *__restrict__ b_b0,
            const float *__restrict__ Wih_b1, const float *__restrict__ Whh_b1, const float *__restrict__ b_b1,
            const float *__restrict__ Wlin,   const float *__restrict__ blin,
            const int *__restrict__ future_p,
            float *__restrict__ out)
{
    const int tid  = threadIdx.x;
    const int j    = tid & 127;
    const bool isF = tid < 128;
    const int nb0  = blockIdx.x * NB;

    __shared__ __align__(16) float hf0s[NB][HP];
    __shared__ __align__(16) float hf1s[4][NB][HP];   // depth-4 ring
    __shared__ __align__(16) float hb0s[NB][HP];
    __shared__ __align__(16) float hb1s[2][NB][HP];   // parity pair
    __shared__ float cf0s[NB][HID], cf1s[NB][HID], cb0s[NB][HID], cb1s[NB][HID];
    __shared__ float gF0[NB][GATES], gF1[NB][GATES];
    __shared__ float gB0[NB][GATES];
    __shared__ float gB1[2][NB][GATES];               // parity pair (deferred fin)
    __shared__ float xs[NB], xbs[NB];
    __shared__ __align__(16) float wls[2 * HID];
    __shared__ float blin_s;

    u64 w0[16], w1[16], w2[16];
    float bias0, bias1, wx;
    if (isF) {
        load_row(w0, Whh_f0 + j * HID);
        load_row(w1, Wih_f1 + j * HID);
        load_row(w2, Whh_f1 + j * HID);
        bias0 = b_f0[j]; bias1 = b_f1[j]; wx = Wih_f0[j];
    } else {
        load_row(w0, Whh_b0 + j * HID);
        load_row(w1, Wih_b1 + j * HID);
        load_row(w2, Whh_b1 + j * HID);   // on hf1 (replicated bug)
        bias0 = b_b0[j]; bias1 = b_b1[j]; wx = Wih_b0[j];
    }
    const int fut = future_p[0];
    const float *xbase = x + nb0;
    const bool jval = (j < NB) && (nb0 + j < B_TOT);

    for (int i = tid; i < NB * HP; i += 256) {
        ((float *)hf0s)[i] = 0.f; ((float *)hb0s)[i] = 0.f;
    }
    for (int i = tid; i < 4 * NB * HP; i += 256) ((float *)hf1s)[i] = 0.f;
    for (int i = tid; i < 2 * NB * HP; i += 256) ((float *)hb1s)[i] = 0.f;
    for (int i = tid; i < NB * HID; i += 256) {
        ((float *)cf0s)[i] = 0.f; ((float *)cf1s)[i] = 0.f;
        ((float *)cb0s)[i] = 0.f; ((float *)cb1s)[i] = 0.f;
    }
    if (tid < 2 * HID) wls[tid] = Wlin[tid];
    if (tid == 0) blin_s = blin[0];

    int rb = fut % S_LEN; if (rb < 0) rb += S_LEN;     // backward index for t=0

    if (tid < NB) {
        xs[tid] = jval ? xbase[tid] : 0.f;
    } else if (tid >= 128 && tid < 128 + NB) {
        xbs[tid - 128] = jval ? xbase[rb * B_TOT + (tid - 128)] : 0.f;
    }
    rb--; if (rb < 0) rb += S_LEN;                     // index for t=1

    __syncthreads();

    const int m  = j & 31;
    const int ng = j >> 5;

    // prologue: f0_0 from zero state
    if (isF) {
#pragma unroll
        for (int n = 0; n < NB; n++) gF0[n][j] = bias0 + wx * xs[n];
    }
    __syncthreads();
    if (isF) {
        if (ng < 3) cell2(gF0[ng], cf0s[ng], hf0s[ng],
                          gF0[ng + 4], cf0s[ng + 4], hf0s[ng + 4], m);
        else        cell1(gF0[3], cf0s[3], hf0s[3], m);
    }
    if (tid < NB) xs[tid] = jval ? xbase[B_TOT + tid] : 0.f;   // x_1
    __syncthreads();

    // iter t: F-comp: f0_{t+1}/f1_t gates + out_{t-3}.  B-comp: b1_{t-2} fin
    // (deferred) + b0_t/b1_{t-1} gates.  F-fin: f0,f1.  B-fin: b0 only.
    for (int t = 0; t < S_LEN + 3; t++) {
        const int rslot = (t + 3) & 3;   // hf1_{t-1}
        const int wslot = t & 3;         // hf1_t (written in F fin)
        const int oslot = (t + 1) & 3;   // hf1_{t-3}
        float xreg = 0.f, xbreg = 0.f;

        // ==== compute ====
        if (isF) {
            if (t < S_LEN) {
                if (jval && t + 2 < S_LEN) xreg = xbase[(t + 2) * B_TOT + j];
                const float *hvb = hf1s[rslot][0];
#pragma unroll
                for (int n = 0; n < NB; n++) {
                    u64 a0 = 0, a1 = 0, a2 = 0, a3 = 0, a4 = 0, a5 = 0;
                    const ulonglong2 *hu = (const ulonglong2 *)hf0s[n];
                    const ulonglong2 *hv = (const ulonglong2 *)(hvb + n * HP);
#pragma unroll
                    for (int c = 0; c < 8; c++) {
                        ulonglong2 u = hu[c];
                        fma2(a0, w0[2 * c],     u.x);
                        fma2(a1, w0[2 * c + 1], u.y);
                        fma2(a2, w1[2 * c],     u.x);
                        fma2(a3, w1[2 * c + 1], u.y);
                        ulonglong2 v = hv[c];
                        fma2(a4, w2[2 * c],     v.x);
                        fma2(a5, w2[2 * c + 1], v.y);
                    }
                    add2(a0, a1);
                    gF0[n][j] = hsum2(a0) + bias0 + wx * xs[n];     // f0_{t+1}
                    add2(a2, a3); add2(a4, a5); add2(a2, a4);
                    gF1[n][j] = hsum2(a2) + bias1;                  // f1_t
                }
            }
            // out_{t-3}: hf1_{t-3} (slot oslot), hb1_{t-3} (slot (t-3)&1=(t+1)&1,
            // written at B-comp(t-1), full barrier since)
            if (t >= 3 && j >= 120) {
                int n = j - 120;
                if (n < NB && nb0 + n < B_TOT) {
                    const ulonglong2 *pf = (const ulonglong2 *)hf1s[oslot][n];
                    const ulonglong2 *pk = (const ulonglong2 *)hb1s[(t + 1) & 1][n];
                    const ulonglong2 *wf = (const ulonglong2 *)wls;
                    u64 acc = 0, acc2 = 0;
#pragma unroll
                    for (int c = 0; c < 8; c++) {
                        ulonglong2 u = pf[c], wu = wf[c];
                        fma2(acc,  wu.x, u.x);
                        fma2(acc2, wu.y, u.y);
                        ulonglong2 v = pk[c], wv = wf[c + 8];
                        fma2(acc,  wv.x, v.x);
                        fma2(acc2, wv.y, v.y);
                    }
                    add2(acc, acc2);
                    out[(nb0 + n) * S_LEN + (t - 3)] = hsum2(acc) + blin_s;
                }
            }
        } else {
            // -- deferred b1_{t-2} finalize (gates from comp(t-1), slot (t-1)&1) --
            if (t >= 2 && t <= S_LEN + 1) {
                const float (*gp)[GATES] = gB1[(t + 1) & 1];   // (t-1)&1
                float (*hb)[HP] = hb1s[t & 1];                 // (t-2)&1
                if (ng < 3) cell2(gp[ng], cb1s[ng], hb[ng],
                                  gp[ng + 4], cb1s[ng + 4], hb[ng + 4], m);
                else        cell1(gp[3], cb1s[3], hb[3], m);
            }
            if (t <= S_LEN) {
                if (jval && t + 1 < S_LEN) xbreg = xbase[rb * B_TOT + j];
                const float *hvb = hf1s[rslot][0];
                float (*g1p)[GATES] = gB1[t & 1];
#pragma unroll
                for (int n = 0; n < NB; n++) {
                    u64 a0 = 0, a1 = 0, a2 = 0, a3 = 0, a4 = 0, a5 = 0;
                    const ulonglong2 *hu = (const ulonglong2 *)hb0s[n];
                    const ulonglong2 *hv = (const ulonglong2 *)(hvb + n * HP);
#pragma unroll
                    for (int c = 0; c < 8; c++) {
                        ulonglong2 u = hu[c];
                        fma2(a0, w0[2 * c],     u.x);
                        fma2(a1, w0[2 * c + 1], u.y);
                        fma2(a2, w1[2 * c],     u.x);
                        fma2(a3, w1[2 * c + 1], u.y);
                        ulonglong2 v = hv[c];
                        fma2(a4, w2[2 * c],     v.x);
                        fma2(a5, w2[2 * c + 1], v.y);
                    }
                    add2(a0, a1);
                    gB0[n][j] = hsum2(a0) + bias0 + wx * xbs[n];    // b0_t
                    add2(a2, a3); add2(a4, a5); add2(a2, a4);
                    g1p[n][j] = hsum2(a2) + bias1;                  // b1_{t-1}
                }
            }
            rb--; if (rb < 0) rb += S_LEN;
        }

        // per-half barrier: gates ready within this half
        if (isF) asm volatile("bar.sync 1, 128;" ::: "memory");
        else     asm volatile("bar.sync 2, 128;" ::: "memory");

        // ==== finalize ====
        if (isF) {
            if (t < S_LEN) {
                if (ng < 3) {
                    cell2(gF0[ng], cf0s[ng], hf0s[ng],
                          gF0[ng + 4], cf0s[ng + 4], hf0s[ng + 4], m);         // f0_{t+1}
                    cell2(gF1[ng], cf1s[ng], hf1s[wslot][ng],
                          gF1[ng + 4], cf1s[ng + 4], hf1s[wslot][ng + 4], m);  // f1_t
                } else {
                    cell2(gF0[3], cf0s[3], hf0s[3],
                          gF1[3], cf1s[3], hf1s[wslot][3], m);
                }
                if (j < NB) xs[j] = xreg;                                      // x_{t+2}
            }
        } else {
            if (t < S_LEN) {
                if (ng < 3) cell2(gB0[ng], cb0s[ng], hb0s[ng],
                                  gB0[ng + 4], cb0s[ng + 4], hb0s[ng + 4], m); // b0_t
                else        cell1(gB0[3], cb0s[3], hb0s[3], m);
                if (j < NB) xbs[j] = xbreg;                                    // xb_{t+1}
            }
        }
        __syncthreads();
    }
}

extern "C" void kernel_launch(void *const *d_in, const int *in_sizes, int n_in,
                              void *d_out, int out_size)
{
    const float *x      = (const float *)d_in[0];
    const float *Wih_f0 = (const float *)d_in[1];
    const float *Whh_f0 = (const float *)d_in[2];
    const float *b_f0   = (const float *)d_in[3];
    const float *Wih_f1 = (const float *)d_in[4];
    const float *Whh_f1 = (const float *)d_in[5];
    const float *b_f1   = (const float *)d_in[6];
    const float *Wih_b0 = (const float *)d_in[7];
    const float *Whh_b0 = (const float *)d_in[8];
    const float *b_b0   = (const float *)d_in[9];
    const float *Wih_b1 = (const float *)d_in[10];
    const float *Whh_b1 = (const float *)d_in[11];
    const float *b_b1   = (const float *)d_in[12];
    const float *Wlin   = (const float *)d_in[13];
    const float *blin   = (const float *)d_in[14];
    const int   *future = (const int *)d_in[15];
    float *out = (float *)d_out;

    lstm_kernel<<<NCTA, 256>>>(x,
                               Wih_f0, Whh_f0, b_f0,
                               Wih_f1, Whh_f1, b_f1,
                               Wih_b0, Whh_b0, b_b0,
                               Wih_b1, Whh_b1, b_b1,
                               Wlin, blin, future, out);
}